// round 10
// baseline (speedup 1.0000x reference)
#include <cuda_runtime.h>

#define S_LEN 4096
#define HID 2048
#define NLAYERS 4

// ---------------- scan (recurrence) config ----------------
#define GBLK 64           // persistent blocks (halved: shrink barrier fan-in)
#define ROWS_PER_BLK 32   // 2048 / 64
#define SCAN_TPB 512
#define KGROUPS 16        // 512 threads / 32 rows
#define KPT 128           // 2048 / 16 k-groups

// ---------------- GEMM config ----------------
#define BK 16

// ---------------- scratch (static device globals) ----------
__device__ float g_xw[S_LEN * HID];     // input projection for current layer
__device__ float g_buf0[S_LEN * HID];   // layer output ping
__device__ float g_buf1[S_LEN * HID];   // layer output pong
__device__ float g_h[2][HID];           // hidden-state ping-pong
__device__ unsigned int g_bar;          // grid barrier counter

// ---------------- f32x2 helpers (proven R4/R5) ----------------
__device__ __forceinline__ void fma2(unsigned long long& d, unsigned long long a,
                                     unsigned long long b, unsigned long long c) {
    asm("fma.rn.f32x2 %0, %1, %2, %3;" : "=l"(d) : "l"(a), "l"(b), "l"(c));
}
__device__ __forceinline__ unsigned long long pack2(float lo, float hi) {
    unsigned long long r;
    asm("mov.b64 %0, {%1, %2};" : "=l"(r) : "f"(lo), "f"(hi));
    return r;
}
__device__ __forceinline__ float2 unpack2(unsigned long long v) {
    float2 f;
    asm("mov.b64 {%0, %1}, %2;" : "=f"(f.x), "=f"(f.y) : "l"(v));
    return f;
}

// ---------------------------------------------------------------------------
// reset (frozen): zero barrier counter + hidden state
// ---------------------------------------------------------------------------
__global__ void reset_kernel() {
    int i = threadIdx.x;
    if (i == 0) g_bar = 0u;
    float* h = &g_h[0][0];
    for (int j = i; j < 2 * HID; j += blockDim.x) h[j] = 0.0f;
}

// ---------------------------------------------------------------------------
// GEMM (FROZEN, verbatim from PASSING R4/R5): C[i,j] = sum_k A[i,k]*B[j,k]
// ---------------------------------------------------------------------------
__global__ void __launch_bounds__(256, 2) gemm_kernel(const float* __restrict__ A,
                                                      const float* __restrict__ B,
                                                      float* __restrict__ C) {
    const int K = HID;
    const int N = HID;
    __shared__ float As[2][BK][128];
    __shared__ float Bs[2][BK][128];

    const int tid  = threadIdx.x;
    const int tx   = tid & 15;
    const int ty   = tid >> 4;
    const int lrow = tid >> 1;
    const int lk   = (tid & 1) * 8;

    const float* Ap = A + (size_t)(blockIdx.y * 128 + lrow) * K + lk;
    const float* Bp = B + (size_t)(blockIdx.x * 128 + lrow) * K + lk;

    unsigned long long acc2[8][4];
    const unsigned long long z2 = pack2(0.0f, 0.0f);
#pragma unroll
    for (int i = 0; i < 8; i++)
#pragma unroll
        for (int j = 0; j < 4; j++) acc2[i][j] = z2;

    {
        float4 a0 = *(const float4*)(Ap);
        float4 a1 = *(const float4*)(Ap + 4);
        float4 b0 = *(const float4*)(Bp);
        float4 b1 = *(const float4*)(Bp + 4);
        As[0][lk + 0][lrow] = a0.x; As[0][lk + 1][lrow] = a0.y;
        As[0][lk + 2][lrow] = a0.z; As[0][lk + 3][lrow] = a0.w;
        As[0][lk + 4][lrow] = a1.x; As[0][lk + 5][lrow] = a1.y;
        As[0][lk + 6][lrow] = a1.z; As[0][lk + 7][lrow] = a1.w;
        Bs[0][lk + 0][lrow] = b0.x; Bs[0][lk + 1][lrow] = b0.y;
        Bs[0][lk + 2][lrow] = b0.z; Bs[0][lk + 3][lrow] = b0.w;
        Bs[0][lk + 4][lrow] = b1.x; Bs[0][lk + 5][lrow] = b1.y;
        Bs[0][lk + 6][lrow] = b1.z; Bs[0][lk + 7][lrow] = b1.w;
    }
    __syncthreads();

    int cur = 0;
    for (int k0 = BK; k0 <= K; k0 += BK) {
        float4 na0, na1, nb0, nb1;
        const bool more = (k0 < K);
        if (more) {
            na0 = *(const float4*)(Ap + k0);
            na1 = *(const float4*)(Ap + k0 + 4);
            nb0 = *(const float4*)(Bp + k0);
            nb1 = *(const float4*)(Bp + k0 + 4);
        }

#pragma unroll
        for (int kk = 0; kk < BK; kk++) {
            float4 a0 = *(const float4*)&As[cur][kk][ty * 8];
            float4 a1 = *(const float4*)&As[cur][kk][ty * 8 + 4];
            ulonglong2 bp0 = *(const ulonglong2*)&Bs[cur][kk][tx * 8];
            ulonglong2 bp1 = *(const ulonglong2*)&Bs[cur][kk][tx * 8 + 4];
            float a[8] = {a0.x, a0.y, a0.z, a0.w, a1.x, a1.y, a1.z, a1.w};
#pragma unroll
            for (int i = 0; i < 8; i++) {
                unsigned long long aa = pack2(a[i], a[i]);
                fma2(acc2[i][0], aa, bp0.x, acc2[i][0]);
                fma2(acc2[i][1], aa, bp0.y, acc2[i][1]);
                fma2(acc2[i][2], aa, bp1.x, acc2[i][2]);
                fma2(acc2[i][3], aa, bp1.y, acc2[i][3]);
            }
        }

        if (more) {
            int nxt = cur ^ 1;
            As[nxt][lk + 0][lrow] = na0.x; As[nxt][lk + 1][lrow] = na0.y;
            As[nxt][lk + 2][lrow] = na0.z; As[nxt][lk + 3][lrow] = na0.w;
            As[nxt][lk + 4][lrow] = na1.x; As[nxt][lk + 5][lrow] = na1.y;
            As[nxt][lk + 6][lrow] = na1.z; As[nxt][lk + 7][lrow] = na1.w;
            Bs[nxt][lk + 0][lrow] = nb0.x; Bs[nxt][lk + 1][lrow] = nb0.y;
            Bs[nxt][lk + 2][lrow] = nb0.z; Bs[nxt][lk + 3][lrow] = nb0.w;
            Bs[nxt][lk + 4][lrow] = nb1.x; Bs[nxt][lk + 5][lrow] = nb1.y;
            Bs[nxt][lk + 6][lrow] = nb1.z; Bs[nxt][lk + 7][lrow] = nb1.w;
            __syncthreads();
            cur = nxt;
        }
    }

#pragma unroll
    for (int i = 0; i < 8; i++) {
        float* Cp = C + (size_t)(blockIdx.y * 128 + ty * 8 + i) * N +
                    blockIdx.x * 128 + tx * 8;
        float2 c0 = unpack2(acc2[i][0]);
        float2 c1 = unpack2(acc2[i][1]);
        float2 c2 = unpack2(acc2[i][2]);
        float2 c3 = unpack2(acc2[i][3]);
        *(float4*)(Cp + 0) = make_float4(c0.x, c0.y, c1.x, c1.y);
        *(float4*)(Cp + 4) = make_float4(c2.x, c2.y, c3.x, c3.y);
    }
}

// ---------------------------------------------------------------------------
// Persistent recurrence: h_t = relu(xw_t + W_hh @ h_{t-1})
// Protocol ops FROZEN (= R5): central counter, tid0 red.release arrival,
// tid0 ld.acquire poll, bar relay. Geometry: 64 blocks x 512 threads,
// 32 rows/block, kg = warp (16 k-groups of 128 elems). Publishers = warp 0.
// ---------------------------------------------------------------------------
__global__ void __launch_bounds__(SCAN_TPB, 1) scan_kernel(
    const float* __restrict__ xw, const float* __restrict__ whh,
    float* __restrict__ y, float* __restrict__ hlast) {
    __shared__ float hbuf[HID];
    __shared__ float part[KGROUPS][ROWS_PER_BLK];

    const int tid  = threadIdx.x;
    const int lane = tid & 31;          // row within block
    const int warp = tid >> 5;          // k-group 0..15
    const int k0   = warp * KPT;
    const int rowG = blockIdx.x * ROWS_PER_BLK + lane;
    const int col  = blockIdx.x * ROWS_PER_BLK + tid;  // used when tid<32

    // W_hh slice -> registers as f32x2 pairs (128 floats = 64 u64 regs)
    unsigned long long wp[KPT / 2];
    {
        const float* wr = whh + (size_t)rowG * HID + k0;
#pragma unroll
        for (int i = 0; i < KPT / 4; i++) {
            ulonglong2 v = *(const ulonglong2*)(wr + i * 4);
            wp[2 * i]     = v.x;
            wp[2 * i + 1] = v.y;
        }
    }

    int p = 0;
    for (int t = 0; t < S_LEN; ++t) {
        // prefetch xw early (immutable within the layer)
        float xwv = 0.0f;
        if (tid < ROWS_PER_BLK) xwv = __ldg(&xw[(size_t)t * HID + col]);

        // broadcast h_{t-1}: one float4 per thread, L2 load
        float4 hv4 = __ldcg((const float4*)&g_h[p][tid * 4]);
        *(float4*)&hbuf[tid * 4] = hv4;
        __syncthreads();

        // dot product: 64 packed FFMA2 from register-resident W
        unsigned long long a0, a1, a2, a3;
        a0 = a1 = a2 = a3 = pack2(0.0f, 0.0f);
#pragma unroll
        for (int i = 0; i < KPT / 8; i++) {
            ulonglong2 h0 = *(const ulonglong2*)&hbuf[k0 + i * 8];
            ulonglong2 h1 = *(const ulonglong2*)&hbuf[k0 + i * 8 + 4];
            fma2(a0, wp[4 * i + 0], h0.x, a0);
            fma2(a1, wp[4 * i + 1], h0.y, a1);
            fma2(a2, wp[4 * i + 2], h1.x, a2);
            fma2(a3, wp[4 * i + 3], h1.y, a3);
        }
        float2 f0 = unpack2(a0), f1 = unpack2(a1);
        float2 f2 = unpack2(a2), f3 = unpack2(a3);
        float acc = ((f0.x + f0.y) + (f1.x + f1.y)) +
                    ((f2.x + f2.y) + (f3.x + f3.y));

        // partials: warp == k-group, lane == row -> direct store, no shfl
        part[warp][lane] = acc;
        __syncthreads();

        // final reduce (tree over 16 k-groups) + relu + publish + release
        if (tid < ROWS_PER_BLK) {
            float s01 = part[0][tid]  + part[1][tid];
            float s23 = part[2][tid]  + part[3][tid];
            float s45 = part[4][tid]  + part[5][tid];
            float s67 = part[6][tid]  + part[7][tid];
            float s89 = part[8][tid]  + part[9][tid];
            float sab = part[10][tid] + part[11][tid];
            float scd = part[12][tid] + part[13][tid];
            float sef = part[14][tid] + part[15][tid];
            float s = ((s01 + s23) + (s45 + s67)) + ((s89 + sab) + (scd + sef));
            float hv = fmaxf(s + xwv, 0.0f);
            g_h[p ^ 1][col] = hv;              // protocol state: before release
            __syncwarp();                      // order warp-0 h-stores
            if (tid == 0) {
                asm volatile("red.release.gpu.global.add.u32 [%0], %1;"
                             :: "l"(&g_bar), "r"(1u) : "memory");
            }
            // outputs (read only across kernel boundary): off critical path
            y[(size_t)t * HID + col] = hv;
            if (hlast != nullptr && t == S_LEN - 1) hlast[col] = hv;
        }

        // tid0 polls the counter; bar relays release+visibility to the block
        if (tid == 0) {
            const unsigned target = (unsigned)(t + 1) * (unsigned)GBLK;
            unsigned v;
            do {
                asm volatile("ld.acquire.gpu.global.u32 %0, [%1];"
                             : "=r"(v) : "l"(&g_bar) : "memory");
            } while (v < target);
        }
        __syncthreads();
        p ^= 1;
    }
}

// ---------------------------------------------------------------------------
// host launcher (graph-capturable: kernel launches only)
// ---------------------------------------------------------------------------
extern "C" void kernel_launch(void* const* d_in, const int* in_sizes, int n_in,
                              void* d_out, int out_size) {
    const float* x0  = (const float*)d_in[0];
    const float* wih = (const float*)d_in[1];
    const float* whh = (const float*)d_in[2];
    float* out = (float*)d_out;

    void *p_xw, *p_b0, *p_b1;
    cudaGetSymbolAddress(&p_xw, g_xw);
    cudaGetSymbolAddress(&p_b0, g_buf0);
    cudaGetSymbolAddress(&p_b1, g_buf1);
    float* bufs[2] = {(float*)p_b0, (float*)p_b1};

    float* hlast = (out_size >= S_LEN * HID + HID) ? out + (size_t)S_LEN * HID
                                                   : nullptr;

    const float* x = x0;
    dim3 ggrid(HID / 128, S_LEN / 128);
    for (int L = 0; L < NLAYERS; ++L) {
        reset_kernel<<<1, 512>>>();
        gemm_kernel<<<ggrid, 256>>>(x, wih + (size_t)L * HID * HID, (float*)p_xw);
        float* yout = (L == NLAYERS - 1) ? out : bufs[L & 1];
        scan_kernel<<<GBLK, SCAN_TPB>>>((const float*)p_xw,
                                        whh + (size_t)L * HID * HID, yout,
                                        (L == NLAYERS - 1) ? hlast : nullptr);
        x = yout;
    }
}

// round 11
// speedup vs baseline: 1.4235x; 1.4235x over previous
#include <cuda_runtime.h>

#define S_LEN 4096
#define HID 2048
#define NLAYERS 4

// ---------------- scan (recurrence) config (R5/R9 proven geometry) --------
#define GBLK 128          // persistent blocks; all co-resident
#define ROWS_PER_BLK 16   // 2048 / 128
#define SCAN_TPB 512
#define KPT 64            // k-elements per thread (reg-resident; fits 128-reg cap)

// ---------------- barrier sharding ----------------
#define NBAR 8            // 8 counters; block b arrives on counter b&7
#define BAR_STRIDE 64     // 64 u32 = 256 B between counters (distinct lines)
#define BLKS_PER_BAR (GBLK / NBAR)   // 16 arrivals per counter per step

// ---------------- GEMM config ----------------
#define BK 16

// ---------------- scratch (static device globals) ----------
__device__ float g_xw[S_LEN * HID];     // input projection for current layer
__device__ float g_buf0[S_LEN * HID];   // layer output ping
__device__ float g_buf1[S_LEN * HID];   // layer output pong
__device__ float g_h[2][HID];           // hidden-state ping-pong
__device__ unsigned g_bars[NBAR * BAR_STRIDE];  // sharded barrier counters

// ---------------- f32x2 helpers (proven R4/R5) ----------------
__device__ __forceinline__ void fma2(unsigned long long& d, unsigned long long a,
                                     unsigned long long b, unsigned long long c) {
    asm("fma.rn.f32x2 %0, %1, %2, %3;" : "=l"(d) : "l"(a), "l"(b), "l"(c));
}
__device__ __forceinline__ unsigned long long pack2(float lo, float hi) {
    unsigned long long r;
    asm("mov.b64 %0, {%1, %2};" : "=l"(r) : "f"(lo), "f"(hi));
    return r;
}
__device__ __forceinline__ float2 unpack2(unsigned long long v) {
    float2 f;
    asm("mov.b64 {%0, %1}, %2;" : "=f"(f.x), "=f"(f.y) : "l"(v));
    return f;
}

// ---------------------------------------------------------------------------
// reset: zero all barrier counters + hidden state (per layer)
// ---------------------------------------------------------------------------
__global__ void reset_kernel() {
    int i = threadIdx.x;
    float* h = &g_h[0][0];
    for (int j = i; j < 2 * HID; j += blockDim.x) h[j] = 0.0f;
    for (int j = i; j < NBAR * BAR_STRIDE; j += blockDim.x) g_bars[j] = 0u;
}

// ---------------------------------------------------------------------------
// GEMM (FROZEN, verbatim from PASSING R4/R5): C[i,j] = sum_k A[i,k]*B[j,k]
// ---------------------------------------------------------------------------
__global__ void __launch_bounds__(256, 2) gemm_kernel(const float* __restrict__ A,
                                                      const float* __restrict__ B,
                                                      float* __restrict__ C) {
    const int K = HID;
    const int N = HID;
    __shared__ float As[2][BK][128];
    __shared__ float Bs[2][BK][128];

    const int tid  = threadIdx.x;
    const int tx   = tid & 15;
    const int ty   = tid >> 4;
    const int lrow = tid >> 1;
    const int lk   = (tid & 1) * 8;

    const float* Ap = A + (size_t)(blockIdx.y * 128 + lrow) * K + lk;
    const float* Bp = B + (size_t)(blockIdx.x * 128 + lrow) * K + lk;

    unsigned long long acc2[8][4];
    const unsigned long long z2 = pack2(0.0f, 0.0f);
#pragma unroll
    for (int i = 0; i < 8; i++)
#pragma unroll
        for (int j = 0; j < 4; j++) acc2[i][j] = z2;

    {
        float4 a0 = *(const float4*)(Ap);
        float4 a1 = *(const float4*)(Ap + 4);
        float4 b0 = *(const float4*)(Bp);
        float4 b1 = *(const float4*)(Bp + 4);
        As[0][lk + 0][lrow] = a0.x; As[0][lk + 1][lrow] = a0.y;
        As[0][lk + 2][lrow] = a0.z; As[0][lk + 3][lrow] = a0.w;
        As[0][lk + 4][lrow] = a1.x; As[0][lk + 5][lrow] = a1.y;
        As[0][lk + 6][lrow] = a1.z; As[0][lk + 7][lrow] = a1.w;
        Bs[0][lk + 0][lrow] = b0.x; Bs[0][lk + 1][lrow] = b0.y;
        Bs[0][lk + 2][lrow] = b0.z; Bs[0][lk + 3][lrow] = b0.w;
        Bs[0][lk + 4][lrow] = b1.x; Bs[0][lk + 5][lrow] = b1.y;
        Bs[0][lk + 6][lrow] = b1.z; Bs[0][lk + 7][lrow] = b1.w;
    }
    __syncthreads();

    int cur = 0;
    for (int k0 = BK; k0 <= K; k0 += BK) {
        float4 na0, na1, nb0, nb1;
        const bool more = (k0 < K);
        if (more) {
            na0 = *(const float4*)(Ap + k0);
            na1 = *(const float4*)(Ap + k0 + 4);
            nb0 = *(const float4*)(Bp + k0);
            nb1 = *(const float4*)(Bp + k0 + 4);
        }

#pragma unroll
        for (int kk = 0; kk < BK; kk++) {
            float4 a0 = *(const float4*)&As[cur][kk][ty * 8];
            float4 a1 = *(const float4*)&As[cur][kk][ty * 8 + 4];
            ulonglong2 bp0 = *(const ulonglong2*)&Bs[cur][kk][tx * 8];
            ulonglong2 bp1 = *(const ulonglong2*)&Bs[cur][kk][tx * 8 + 4];
            float a[8] = {a0.x, a0.y, a0.z, a0.w, a1.x, a1.y, a1.z, a1.w};
#pragma unroll
            for (int i = 0; i < 8; i++) {
                unsigned long long aa = pack2(a[i], a[i]);
                fma2(acc2[i][0], aa, bp0.x, acc2[i][0]);
                fma2(acc2[i][1], aa, bp0.y, acc2[i][1]);
                fma2(acc2[i][2], aa, bp1.x, acc2[i][2]);
                fma2(acc2[i][3], aa, bp1.y, acc2[i][3]);
            }
        }

        if (more) {
            int nxt = cur ^ 1;
            As[nxt][lk + 0][lrow] = na0.x; As[nxt][lk + 1][lrow] = na0.y;
            As[nxt][lk + 2][lrow] = na0.z; As[nxt][lk + 3][lrow] = na0.w;
            As[nxt][lk + 4][lrow] = na1.x; As[nxt][lk + 5][lrow] = na1.y;
            As[nxt][lk + 6][lrow] = na1.z; As[nxt][lk + 7][lrow] = na1.w;
            Bs[nxt][lk + 0][lrow] = nb0.x; Bs[nxt][lk + 1][lrow] = nb0.y;
            Bs[nxt][lk + 2][lrow] = nb0.z; Bs[nxt][lk + 3][lrow] = nb0.w;
            Bs[nxt][lk + 4][lrow] = nb1.x; Bs[nxt][lk + 5][lrow] = nb1.y;
            Bs[nxt][lk + 6][lrow] = nb1.z; Bs[nxt][lk + 7][lrow] = nb1.w;
            __syncthreads();
            cur = nxt;
        }
    }

#pragma unroll
    for (int i = 0; i < 8; i++) {
        float* Cp = C + (size_t)(blockIdx.y * 128 + ty * 8 + i) * N +
                    blockIdx.x * 128 + tx * 8;
        float2 c0 = unpack2(acc2[i][0]);
        float2 c1 = unpack2(acc2[i][1]);
        float2 c2 = unpack2(acc2[i][2]);
        float2 c3 = unpack2(acc2[i][3]);
        *(float4*)(Cp + 0) = make_float4(c0.x, c0.y, c1.x, c1.y);
        *(float4*)(Cp + 4) = make_float4(c2.x, c2.y, c3.x, c3.y);
    }
}

// ---------------------------------------------------------------------------
// Persistent recurrence: h_t = relu(xw_t + W_hh @ h_{t-1})
// = R9 (passing) with ONE change: the central counter is sharded into 8
// counters 256B apart. Block b arrives (red.release.gpu.add, identical op)
// on counter b&7; threads tid<8 each run the IDENTICAL R5 poll loop on
// counter tid with target (t+1)*16; __syncthreads relays to the block.
// Monotonic counters -> same termination proof as R5, 8x less fan-in.
// ---------------------------------------------------------------------------
__global__ void __launch_bounds__(SCAN_TPB, 1) scan_kernel(
    const float* __restrict__ xw, const float* __restrict__ whh,
    float* __restrict__ y, float* __restrict__ hlast) {
    __shared__ float hbuf[HID];
    __shared__ float part[16][ROWS_PER_BLK];

    const int tid  = threadIdx.x;
    const int row  = tid & 15;
    const int kg   = tid >> 4;
    const int k0   = kg * KPT;
    const int rowG = blockIdx.x * ROWS_PER_BLK + row;
    const int warp = tid >> 5;
    const int lane = tid & 31;
    const int col  = blockIdx.x * ROWS_PER_BLK + tid;  // used when tid<16
    unsigned* ourbar = &g_bars[(blockIdx.x & (NBAR - 1)) * BAR_STRIDE];

    // W_hh slice -> registers as f32x2 pairs (64 floats = 32 u64: fits regs)
    unsigned long long wp[KPT / 2];
    {
        const float* wr = whh + (size_t)rowG * HID + k0;
#pragma unroll
        for (int i = 0; i < KPT / 4; i++) {
            ulonglong2 v = *(const ulonglong2*)(wr + i * 4);
            wp[2 * i]     = v.x;
            wp[2 * i + 1] = v.y;
        }
    }

    int p = 0;
    for (int t = 0; t < S_LEN; ++t) {
        // prefetch xw early (immutable within the layer)
        float xwv = 0.0f;
        if (tid < ROWS_PER_BLK) xwv = __ldg(&xw[(size_t)t * HID + col]);

        // broadcast h_{t-1}: one float4 per thread, L2 load
        float4 hv4 = __ldcg((const float4*)&g_h[p][tid * 4]);
        *(float4*)&hbuf[tid * 4] = hv4;
        __syncthreads();

        // dot product: 32 packed FFMA2 from register-resident W
        unsigned long long a0, a1, a2, a3;
        a0 = a1 = a2 = a3 = pack2(0.0f, 0.0f);
#pragma unroll
        for (int i = 0; i < KPT / 8; i++) {
            ulonglong2 h0 = *(const ulonglong2*)&hbuf[k0 + i * 8];
            ulonglong2 h1 = *(const ulonglong2*)&hbuf[k0 + i * 8 + 4];
            fma2(a0, wp[4 * i + 0], h0.x, a0);
            fma2(a1, wp[4 * i + 1], h0.y, a1);
            fma2(a2, wp[4 * i + 2], h1.x, a2);
            fma2(a3, wp[4 * i + 3], h1.y, a3);
        }
        float2 f0 = unpack2(a0), f1 = unpack2(a1);
        float2 f2 = unpack2(a2), f3 = unpack2(a3);
        float acc = ((f0.x + f0.y) + (f1.x + f1.y)) +
                    ((f2.x + f2.y) + (f3.x + f3.y));

        // combine the two k-groups living in one warp
        acc += __shfl_down_sync(0xffffffffu, acc, 16);
        if (lane < 16) part[warp][lane] = acc;
        __syncthreads();

        // final reduce (tree) + relu + publish h + sharded release
        if (tid < ROWS_PER_BLK) {
            float s01 = part[0][tid]  + part[1][tid];
            float s23 = part[2][tid]  + part[3][tid];
            float s45 = part[4][tid]  + part[5][tid];
            float s67 = part[6][tid]  + part[7][tid];
            float s89 = part[8][tid]  + part[9][tid];
            float sab = part[10][tid] + part[11][tid];
            float scd = part[12][tid] + part[13][tid];
            float sef = part[14][tid] + part[15][tid];
            float s = ((s01 + s23) + (s45 + s67)) + ((s89 + sab) + (scd + sef));
            float hv = fmaxf(s + xwv, 0.0f);
            g_h[p ^ 1][col] = hv;              // protocol state: before release
            __syncwarp(0x0000ffffu);           // order 16 h-stores in warp 0
            if (tid == 0) {
                asm volatile("red.release.gpu.global.add.u32 [%0], %1;"
                             :: "l"(ourbar), "r"(1u) : "memory");
            }
            // outputs (read only across kernel boundary): off critical path
            y[(size_t)t * HID + col] = hv;
            if (hlast != nullptr && t == S_LEN - 1) hlast[col] = hv;
        }

        // threads 0..7 each poll their own counter (R5 loop x8); bar relays
        if (tid < NBAR) {
            const unsigned target = (unsigned)(t + 1) * (unsigned)BLKS_PER_BAR;
            const unsigned* bp = &g_bars[tid * BAR_STRIDE];
            unsigned v;
            do {
                asm volatile("ld.acquire.gpu.global.u32 %0, [%1];"
                             : "=r"(v) : "l"(bp) : "memory");
            } while (v < target);
        }
        __syncthreads();
        p ^= 1;
    }
}

// ---------------------------------------------------------------------------
// host launcher (graph-capturable: kernel launches only)
// ---------------------------------------------------------------------------
extern "C" void kernel_launch(void* const* d_in, const int* in_sizes, int n_in,
                              void* d_out, int out_size) {
    const float* x0  = (const float*)d_in[0];
    const float* wih = (const float*)d_in[1];
    const float* whh = (const float*)d_in[2];
    float* out = (float*)d_out;

    void *p_xw, *p_b0, *p_b1;
    cudaGetSymbolAddress(&p_xw, g_xw);
    cudaGetSymbolAddress(&p_b0, g_buf0);
    cudaGetSymbolAddress(&p_b1, g_buf1);
    float* bufs[2] = {(float*)p_b0, (float*)p_b1};

    float* hlast = (out_size >= S_LEN * HID + HID) ? out + (size_t)S_LEN * HID
                                                   : nullptr;

    const float* x = x0;
    dim3 ggrid(HID / 128, S_LEN / 128);
    for (int L = 0; L < NLAYERS; ++L) {
        reset_kernel<<<1, 512>>>();
        gemm_kernel<<<ggrid, 256>>>(x, wih + (size_t)L * HID * HID, (float*)p_xw);
        float* yout = (L == NLAYERS - 1) ? out : bufs[L & 1];
        scan_kernel<<<GBLK, SCAN_TPB>>>((const float*)p_xw,
                                        whh + (size_t)L * HID * HID, yout,
                                        (L == NLAYERS - 1) ? hlast : nullptr);
        x = yout;
    }
}